// round 2
// baseline (speedup 1.0000x reference)
#include <cuda_runtime.h>
#include <math.h>

// Problem constants
#define BB   512
#define NN   196
#define CC   384
#define HH   14      // spatial grid 14x14
#define WHALF 8      // rfft half-spectrum width

// Scratch: h kernel per channel, transposed layout [spatial=196][channel=384]
// so that channel-adjacent threads load coalesced.
__device__ float g_h[NN * CC];

// ---------------------------------------------------------------------------
// Kernel 1: build real-space circular-conv kernel h_c = (1/196) * IDFT(W~_c)
// W~ = Hermitian completion of half-spectrum w[14,8,C,2], with the v=0 and
// v=7 (Nyquist) columns symmetrized in u (c2r ignores their anti-Hermitian
// part).
// grid: 384 blocks (one per channel), 196 threads (one per (r,cc)).
// ---------------------------------------------------------------------------
__global__ void build_h_kernel(const float* __restrict__ w) {
    __shared__ float ct[HH];
    __shared__ float st[HH];
    int c  = blockIdx.x;
    int t  = threadIdx.x;          // 0..195
    if (t < HH) {
        double a = 2.0 * 3.14159265358979323846 * (double)t / 14.0;
        ct[t] = (float)cos(a);
        st[t] = (float)sin(a);
    }
    __syncthreads();

    int r  = t / HH;
    int cc = t % HH;

    float acc = 0.0f;
    #pragma unroll 1
    for (int u = 0; u < HH; ++u) {
        #pragma unroll 1
        for (int v = 0; v < HH; ++v) {
            float wr, wi;
            if (v <= 7) {
                int base = ((u * WHALF + v) * CC + c) * 2;
                wr = w[base];
                wi = w[base + 1];
                if (v == 0 || v == 7) {
                    int u2 = (HH - u) % HH;
                    int b2 = ((u2 * WHALF + v) * CC + c) * 2;
                    wr = 0.5f * (wr + w[b2]);
                    wi = 0.5f * (wi - w[b2 + 1]);
                }
            } else {
                int u2 = (HH - u) % HH;
                int v2 = HH - v;
                int b2 = ((u2 * WHALF + v2) * CC + c) * 2;
                wr =  w[b2];
                wi = -w[b2 + 1];
            }
            int k = (u * r + v * cc) % HH;
            // Re( (wr + i wi) * e^{+i 2pi k/14} ) = wr*cos - wi*sin
            acc += wr * ct[k] - wi * st[k];
        }
    }
    g_h[t * CC + c] = acc * (1.0f / 196.0f);
}

// ---------------------------------------------------------------------------
// Packed f32x2 helpers (Blackwell; only reachable from PTX, not C++ autofuse)
// ---------------------------------------------------------------------------
__device__ __forceinline__ unsigned long long pack2(float lo, float hi) {
    unsigned long long r;
    asm("mov.b64 %0, {%1, %2};" : "=l"(r) : "f"(lo), "f"(hi));
    return r;
}
__device__ __forceinline__ void unpack2(unsigned long long v, float& lo, float& hi) {
    asm("mov.b64 {%0, %1}, %2;" : "=f"(lo), "=f"(hi) : "l"(v));
}
__device__ __forceinline__ unsigned long long fma2(
    unsigned long long a, unsigned long long b, unsigned long long c) {
    unsigned long long d;
    asm("fma.rn.f32x2 %0, %1, %2, %3;" : "=l"(d) : "l"(a), "l"(b), "l"(c));
    return d;
}

// ---------------------------------------------------------------------------
// Kernel 2: per-channel circular convolution, f32x2-packed over the two
// register-blocked output rows.
// out[b,p,c] = sum_q x[b,q,c] * h_c[(pr-qr)%14, (pc-qc)%14]
// block = 128 threads (128 channels), grid = (512 batches, 3 channel tiles).
// ---------------------------------------------------------------------------
__global__ __launch_bounds__(128) void gf_conv_kernel(
    const float* __restrict__ x, float* __restrict__ out) {

    int b = blockIdx.x;
    int c = blockIdx.y * 128 + threadIdx.x;

    const float* xb = x   + (size_t)b * (NN * CC) + c;
    float*       ob = out + (size_t)b * (NN * CC) + c;
    const float* hb = g_h + c;   // hb[d*CC] = h_c[d]

    #pragma unroll 1
    for (int pr = 0; pr < HH; pr += 2) {
        unsigned long long accp[HH];   // lo = row pr, hi = row pr+1
        #pragma unroll
        for (int i = 0; i < HH; ++i) accp[i] = 0ull;

        #pragma unroll 1
        for (int qr = 0; qr < HH; ++qr) {
            int d0 = pr - qr;      if (d0 < 0) d0 += HH;
            int d1 = d0 + 1;       if (d1 >= HH) d1 -= HH;

            float xq[HH];
            unsigned long long hp[HH];
            #pragma unroll
            for (int j = 0; j < HH; ++j)
                xq[j] = __ldg(&xb[(qr * HH + j) * CC]);
            #pragma unroll
            for (int j = 0; j < HH; ++j) {
                float h0 = __ldg(&hb[(d0 * HH + j) * CC]);
                float h1 = __ldg(&hb[(d1 * HH + j) * CC]);
                hp[j] = pack2(h0, h1);
            }

            #pragma unroll
            for (int qc = 0; qc < HH; ++qc) {
                unsigned long long xp = pack2(xq[qc], xq[qc]);
                #pragma unroll
                for (int pc = 0; pc < HH; ++pc) {
                    int dd = pc - qc; if (dd < 0) dd += HH;  // compile-time
                    accp[pc] = fma2(xp, hp[dd], accp[pc]);
                }
            }
        }

        #pragma unroll
        for (int pc = 0; pc < HH; ++pc) {
            float a0, a1;
            unpack2(accp[pc], a0, a1);
            ob[( pr      * HH + pc) * CC] = a0;
            ob[((pr + 1) * HH + pc) * CC] = a1;
        }
    }
}

// ---------------------------------------------------------------------------
extern "C" void kernel_launch(void* const* d_in, const int* in_sizes, int n_in,
                              void* d_out, int out_size) {
    const float* x = (const float*)d_in[0];               // [512,196,384]
    const float* w = (const float*)d_in[1];               // [14,8,384,2]
    float*       o = (float*)d_out;                        // [512,196,384]

    build_h_kernel<<<CC, NN>>>(w);
    dim3 grid(BB, CC / 128, 1);
    gf_conv_kernel<<<grid, 128>>>(x, o);
}

// round 13
// speedup vs baseline: 3.1562x; 3.1562x over previous
#include <cuda_runtime.h>
#include <math.h>

// Problem constants
#define BB   512
#define NN   196
#define CC   384
#define HH   14      // spatial grid 14x14
#define WHALF 8      // rfft half-spectrum width

// Scratch: h kernel per channel, transposed layout [spatial=196][channel=384]
// so that channel-adjacent threads load coalesced.
__device__ float g_h[NN * CC];

// ---------------------------------------------------------------------------
// Kernel 1: build real-space circular-conv kernel h_c = (1/196) * IDFT(W~_c)
// W~ = Hermitian completion of half-spectrum w[14,8,C,2]; v=0 and v=7
// (Nyquist) columns symmetrized in u (c2r ignores their anti-Hermitian part).
// ---------------------------------------------------------------------------
__global__ void build_h_kernel(const float* __restrict__ w) {
    __shared__ float ct[HH];
    __shared__ float st[HH];
    int c  = blockIdx.x;
    int t  = threadIdx.x;          // 0..195
    if (t < HH) {
        double a = 2.0 * 3.14159265358979323846 * (double)t / 14.0;
        ct[t] = (float)cos(a);
        st[t] = (float)sin(a);
    }
    __syncthreads();

    int r  = t / HH;
    int cc = t % HH;

    float acc = 0.0f;
    #pragma unroll 1
    for (int u = 0; u < HH; ++u) {
        #pragma unroll 1
        for (int v = 0; v < HH; ++v) {
            float wr, wi;
            if (v <= 7) {
                int base = ((u * WHALF + v) * CC + c) * 2;
                wr = w[base];
                wi = w[base + 1];
                if (v == 0 || v == 7) {
                    int u2 = (HH - u) % HH;
                    int b2 = ((u2 * WHALF + v) * CC + c) * 2;
                    wr = 0.5f * (wr + w[b2]);
                    wi = 0.5f * (wi - w[b2 + 1]);
                }
            } else {
                int u2 = (HH - u) % HH;
                int v2 = HH - v;
                int b2 = ((u2 * WHALF + v2) * CC + c) * 2;
                wr =  w[b2];
                wi = -w[b2 + 1];
            }
            int k = (u * r + v * cc) % HH;
            acc += wr * ct[k] - wi * st[k];
        }
    }
    g_h[t * CC + c] = acc * (1.0f / 196.0f);
}

// ---------------------------------------------------------------------------
// Packed f32x2 helpers (Blackwell; only reachable from PTX, not C++ autofuse)
// ---------------------------------------------------------------------------
__device__ __forceinline__ unsigned long long pack2(float lo, float hi) {
    unsigned long long r;
    asm("mov.b64 %0, {%1, %2};" : "=l"(r) : "f"(lo), "f"(hi));
    return r;
}
__device__ __forceinline__ void unpack2(unsigned long long v, float& lo, float& hi) {
    asm("mov.b64 {%0, %1}, %2;" : "=f"(lo), "=f"(hi) : "l"(v));
}
__device__ __forceinline__ unsigned long long fma2(
    unsigned long long a, unsigned long long b, unsigned long long c) {
    unsigned long long d;
    asm("fma.rn.f32x2 %0, %1, %2, %3;" : "=l"(d) : "l"(a), "l"(b), "l"(c));
    return d;
}

// ---------------------------------------------------------------------------
// Kernel 2: per-channel circular convolution, f32x2-packed over two output
// rows, SOFTWARE-PIPELINED (loads for iteration qr+1 issued before the
// 196-FMA block of iteration qr) AND pr-pair split across blockIdx.z so that
// ample resident warps (TLP) back up the pipeline (ILP) for latency hiding.
// out[b,p,c] = sum_q x[b,q,c] * h_c[(pr-qr)%14, (pc-qc)%14]
// block = 128 threads (128 channels); grid = (512 batches, 3 c-tiles, 7 pr-pairs).
// ---------------------------------------------------------------------------
__global__ __launch_bounds__(128) void gf_conv_kernel(
    const float* __restrict__ x, float* __restrict__ out) {

    int b  = blockIdx.x;
    int c  = blockIdx.y * 128 + threadIdx.x;
    int pr = blockIdx.z * 2;                     // this block's output row pair

    const float* xb = x   + (size_t)b * (NN * CC) + c;
    float*       ob = out + (size_t)b * (NN * CC) + c;
    const float* hb = g_h + c;   // hb[d*CC] = h_c[d]

    unsigned long long accp[HH];   // lo = row pr, hi = row pr+1
    #pragma unroll
    for (int i = 0; i < HH; ++i) accp[i] = 0ull;

    // ---- prologue: loads for qr = 0 (d0 = pr, d1 = pr+1) ----
    float xq[HH], h0r[HH], h1r[HH];
    #pragma unroll
    for (int j = 0; j < HH; ++j) {
        xq[j]  = __ldg(&xb[j * CC]);                       // row 0
        h0r[j] = __ldg(&hb[( pr      * HH + j) * CC]);
        h1r[j] = __ldg(&hb[((pr + 1) * HH + j) * CC]);
    }

    #pragma unroll 1
    for (int qr = 0; qr < HH; ++qr) {
        // snapshot + pack current operands (alu/mov pipe, dual-issues with
        // fma); after this, xq/h0r/h1r are free to be overwritten
        unsigned long long hp[HH], xp[HH];
        #pragma unroll
        for (int j = 0; j < HH; ++j) {
            hp[j] = pack2(h0r[j], h1r[j]);
            xp[j] = pack2(xq[j], xq[j]);
        }

        // ---- prefetch operands for qr+1 (in flight during FMAs) ----
        if (qr < HH - 1) {
            int qn  = qr + 1;
            int nd0 = pr - qn;      if (nd0 < 0) nd0 += HH;
            int nd1 = nd0 + 1;      if (nd1 >= HH) nd1 -= HH;
            #pragma unroll
            for (int j = 0; j < HH; ++j) {
                xq[j]  = __ldg(&xb[(qn * HH + j) * CC]);
                h0r[j] = __ldg(&hb[(nd0 * HH + j) * CC]);
                h1r[j] = __ldg(&hb[(nd1 * HH + j) * CC]);
            }
        }

        // ---- 196 pure packed FMAs on the snapshot ----
        #pragma unroll
        for (int qc = 0; qc < HH; ++qc) {
            #pragma unroll
            for (int pc = 0; pc < HH; ++pc) {
                int dd = pc - qc; if (dd < 0) dd += HH;  // compile-time
                accp[pc] = fma2(xp[qc], hp[dd], accp[pc]);
            }
        }
    }

    #pragma unroll
    for (int pc = 0; pc < HH; ++pc) {
        float a0, a1;
        unpack2(accp[pc], a0, a1);
        ob[( pr      * HH + pc) * CC] = a0;
        ob[((pr + 1) * HH + pc) * CC] = a1;
    }
}

// ---------------------------------------------------------------------------
extern "C" void kernel_launch(void* const* d_in, const int* in_sizes, int n_in,
                              void* d_out, int out_size) {
    const float* x = (const float*)d_in[0];               // [512,196,384]
    const float* w = (const float*)d_in[1];               // [14,8,384,2]
    float*       o = (float*)d_out;                        // [512,196,384]

    build_h_kernel<<<CC, NN>>>(w);
    dim3 grid(BB, CC / 128, HH / 2);
    gf_conv_kernel<<<grid, 128>>>(x, o);
}